// round 4
// baseline (speedup 1.0000x reference)
#include <cuda_runtime.h>
#include <cstdint>
#include <cstddef>

#define S     8192
#define LC    16
#define CH    64
#define HW    256
#define TAGS  50

typedef unsigned long long ull;

// ---------------- device scratch ----------------
__device__ __align__(256) float g_char_feat[S * CH];        // 2 MB
__device__ __align__(256) float g_gpre[(size_t)S * 4 * HW]; // 32 MB
__device__ __align__(256) float g_wh[(size_t)S * HW];       // 8 MB

// ---------------- helpers ----------------
__device__ __forceinline__ ull ffma2(ull a, ull b, ull c) {
    ull d;
    asm("fma.rn.f32x2 %0, %1, %2, %3;" : "=l"(d) : "l"(a), "l"(b), "l"(c));
    return d;
}
__device__ __forceinline__ float f2sum(ull a) {
    float lo = __uint_as_float((unsigned)(a & 0xffffffffull));
    float hi = __uint_as_float((unsigned)(a >> 32));
    return lo + hi;
}
__device__ __forceinline__ float tanha(float x) {
    float y; asm("tanh.approx.f32 %0, %1;" : "=f"(y) : "f"(x)); return y;
}
__device__ __forceinline__ float sigm(float x) {       // 1 MUFU
    return fmaf(0.5f, tanha(0.5f * x), 0.5f);
}
__device__ __forceinline__ uint32_t smem_u32(const void* p) {
    return (uint32_t)__cvta_generic_to_shared(p);
}
__device__ __forceinline__ uint32_t cluster_rank() {
    uint32_t r; asm("mov.u32 %0, %%cluster_ctarank;" : "=r"(r)); return r;
}
__device__ __forceinline__ uint32_t mapa_sh(uint32_t addr, uint32_t rank) {
    uint32_t r;
    asm("mapa.shared::cluster.u32 %0, %1, %2;" : "=r"(r) : "r"(addr), "r"(rank));
    return r;
}
__device__ __forceinline__ void mbar_init(uint32_t addr, uint32_t cnt) {
    asm volatile("mbarrier.init.shared.b64 [%0], %1;" :: "r"(addr), "r"(cnt) : "memory");
}
__device__ __forceinline__ void mbar_expect_tx(uint32_t addr, uint32_t bytes) {
    asm volatile("mbarrier.arrive.expect_tx.shared.b64 _, [%0], %1;"
                 :: "r"(addr), "r"(bytes) : "memory");
}
__device__ __forceinline__ void st_async_v2b64(uint32_t dst, ull v0, ull v1, uint32_t mbar) {
    asm volatile("st.async.shared::cluster.mbarrier::complete_tx::bytes.v2.b64 [%0], {%1, %2}, [%3];"
                 :: "r"(dst), "l"(v0), "l"(v1), "r"(mbar) : "memory");
}
__device__ __forceinline__ void mbar_wait_parity(uint32_t mbar, uint32_t parity) {
    asm volatile(
        "{\n\t.reg .pred P;\n"
        "W%=:\n\t"
        "mbarrier.try_wait.parity.acquire.cluster.shared::cta.b64 P, [%0], %1, 0x989680;\n\t"
        "@!P bra W%=;\n\t"
        "}" :: "r"(mbar), "r"(parity) : "memory");
}
__device__ __forceinline__ void cluster_sync_() {
    asm volatile("barrier.cluster.arrive.aligned;\n\tbarrier.cluster.wait.aligned;" ::: "memory");
}

// =====================================================================
// Kernel 1: char LSTM (fast activations; otherwise as round 3)
// =====================================================================
#define CA_SW   (512 * 68)
#define CA_EMB  (128 * 64)
#define CA_HB   (32 * 64)
#define CA_SB   256
#define CHAR_SMEM_BYTES ((CA_SW + CA_EMB + CA_HB + CA_SB) * 4 + 512 * 4)

__global__ void __launch_bounds__(512, 1)
char_lstm_kernel(const int* __restrict__ ci_g, const int* __restrict__ clen,
                 const float* __restrict__ cemb_g,
                 const float* __restrict__ Wih, const float* __restrict__ Whh,
                 const float* __restrict__ bih, const float* __restrict__ bhh)
{
    extern __shared__ float smA[];
    float* sW    = smA;
    float* cemb  = sW + CA_SW;
    float* hbuf  = cemb + CA_EMB;
    float* sb    = hbuf + CA_HB;
    int*   scidx = (int*)(sb + CA_SB);

    const int tid = threadIdx.x;
    const int wbase = blockIdx.x * 32;

    for (int idx = tid; idx < 512 * 16; idx += 512) {
        int row = idx >> 4, k4 = idx & 15;
        const float* src = (row < 256) ? Wih + (size_t)row * 64 + k4 * 4
                                       : Whh + (size_t)(row - 256) * 64 + k4 * 4;
        *(float4*)&sW[row * 68 + k4 * 4] = *(const float4*)src;
    }
    for (int idx = tid; idx < 128 * 16; idx += 512) {
        int row = idx >> 4, k4 = idx & 15;
        *(float4*)&cemb[row * 64 + k4 * 4] = *(const float4*)(cemb_g + (size_t)row * 64 + k4 * 4);
    }
    if (tid < 256) sb[tid] = bih[tid] + bhh[tid];
    scidx[tid] = ci_g[(size_t)wbase * 16 + tid];
    for (int idx = tid; idx < CA_HB; idx += 512) hbuf[idx] = 0.f;

    const int rt = tid & 63, wt = tid >> 6, w0 = wt * 4;
    int len[4]; float cc[4];
    #pragma unroll
    for (int i = 0; i < 4; i++) { len[i] = clen[wbase + w0 + i]; cc[i] = 0.f; }
    __syncthreads();

    for (int t = 0; t < LC; t++) {
        int ci[4];
        #pragma unroll
        for (int i = 0; i < 4; i++) ci[i] = scidx[(w0 + i) * 16 + t];

        ull acc[4][4];
        #pragma unroll
        for (int i = 0; i < 4; i++)
            #pragma unroll
            for (int q = 0; q < 4; q++) acc[i][q] = 0ull;

        #pragma unroll
        for (int k4 = 0; k4 < 16; k4++) {
            ulonglong2 wv[4];
            #pragma unroll
            for (int q = 0; q < 4; q++)
                wv[q] = *(const ulonglong2*)&sW[(q * 64 + rt) * 68 + k4 * 4];
            #pragma unroll
            for (int i = 0; i < 4; i++) {
                ulonglong2 xv = *(const ulonglong2*)&cemb[ci[i] * 64 + k4 * 4];
                #pragma unroll
                for (int q = 0; q < 4; q++) {
                    acc[i][q] = ffma2(xv.x, wv[q].x, acc[i][q]);
                    acc[i][q] = ffma2(xv.y, wv[q].y, acc[i][q]);
                }
            }
        }
        #pragma unroll
        for (int k4 = 0; k4 < 16; k4++) {
            ulonglong2 wv[4];
            #pragma unroll
            for (int q = 0; q < 4; q++)
                wv[q] = *(const ulonglong2*)&sW[(256 + q * 64 + rt) * 68 + k4 * 4];
            #pragma unroll
            for (int i = 0; i < 4; i++) {
                ulonglong2 hv = *(const ulonglong2*)&hbuf[(w0 + i) * 64 + k4 * 4];
                #pragma unroll
                for (int q = 0; q < 4; q++) {
                    acc[i][q] = ffma2(hv.x, wv[q].x, acc[i][q]);
                    acc[i][q] = ffma2(hv.y, wv[q].y, acc[i][q]);
                }
            }
        }
        __syncthreads();

        float bI = sb[rt], bF = sb[64 + rt], bG = sb[128 + rt], bO = sb[192 + rt];
        #pragma unroll
        for (int i = 0; i < 4; i++) {
            float gi = f2sum(acc[i][0]) + bI;
            float gf = f2sum(acc[i][1]) + bF;
            float gG = f2sum(acc[i][2]) + bG;
            float go = f2sum(acc[i][3]) + bO;
            cc[i] = fmaf(sigm(gf), cc[i], sigm(gi) * tanha(gG));
            float h = sigm(go) * tanha(cc[i]);
            hbuf[(w0 + i) * 64 + rt] = h;
            if (t == len[i] - 1)
                g_char_feat[(size_t)(wbase + w0 + i) * 64 + rt] = h;
        }
        __syncthreads();
    }
}

// =====================================================================
// Kernel 2: gpre (unchanged)
// =====================================================================
#define BP 196
#define GPRE_SMEM_BYTES ((16 + 64) * BP * 4)

__global__ void __launch_bounds__(256, 1)
gpre_kernel(const int* __restrict__ widx, const float* __restrict__ wemb,
            const float* __restrict__ Wih,
            const float* __restrict__ bih, const float* __restrict__ bhh)
{
    extern __shared__ float smB[];
    float* sx = smB;
    float* sw = smB + 16 * BP;

    const int tid = threadIdx.x;
    const int t0 = blockIdx.x * 16;
    const int G0 = blockIdx.y * 64;

    for (int i = tid; i < 16 * 48; i += 256) {
        int tt = i / 48, k4 = i % 48;
        float4 v = (k4 < 32)
            ? *(const float4*)(wemb + (size_t)widx[t0 + tt] * 128 + k4 * 4)
            : *(const float4*)(g_char_feat + (size_t)(t0 + tt) * 64 + (k4 - 32) * 4);
        *(float4*)&sx[tt * BP + k4 * 4] = v;
    }
    for (int i = tid; i < 64 * 48; i += 256) {
        int r = i / 48, k4 = i % 48;
        *(float4*)&sw[r * BP + k4 * 4] = *(const float4*)(Wih + (size_t)(G0 + r) * 192 + k4 * 4);
    }
    __syncthreads();

    const int g = tid & 63, tq = tid >> 6;
    ull ax[4], ay[4];
    #pragma unroll
    for (int i = 0; i < 4; i++) { ax[i] = 0ull; ay[i] = 0ull; }

    #pragma unroll 4
    for (int k4 = 0; k4 < 48; k4++) {
        ulonglong2 wv = *(const ulonglong2*)&sw[g * BP + k4 * 4];
        #pragma unroll
        for (int it = 0; it < 4; it++) {
            ulonglong2 xv = *(const ulonglong2*)&sx[(tq * 4 + it) * BP + k4 * 4];
            ax[it] = ffma2(xv.x, wv.x, ax[it]);
            ay[it] = ffma2(xv.y, wv.y, ay[it]);
        }
    }
    float b = bih[G0 + g] + bhh[G0 + g];
    #pragma unroll
    for (int it = 0; it < 4; it++)
        g_gpre[(size_t)(t0 + tq * 4 + it) * 1024 + G0 + g] = f2sum(ax[it]) + f2sum(ay[it]) + b;
}

// =====================================================================
// Kernel 3: word LSTM. 8-CTA cluster, st.async tx barriers,
// v2.b64 packed broadcast (64 messages per dest barrier per step),
// fast tanh.approx epilogue.
// =====================================================================
__global__ void __launch_bounds__(256, 1) __cluster_dims__(8, 1, 1)
word_lstm_kernel(const float* __restrict__ Whh)
{
    __shared__ float sh[2][256];
    __shared__ __align__(8) unsigned long long bar2[2];

    const int tid = threadIdx.x;
    const int jj  = tid >> 3;     // 0..31 h-unit
    const int oct = tid & 7;      // k octant
    const uint32_t rank = cluster_rank();
    const int uglob = (int)rank * 32 + jj;

    // weights: rw[q][m] covers gate row (q*256 + uglob), k = oct*4 + m*32
    ulonglong2 rw0[8], rw1[8], rw2[8], rw3[8];
    {
        const float* base = Whh + (size_t)uglob * 256 + oct * 4;
        #pragma unroll
        for (int m = 0; m < 8; m++) {
            rw0[m] = *(const ulonglong2*)(base + 0 * 256 * 256 + m * 32);
            rw1[m] = *(const ulonglong2*)(base + 1 * 256 * 256 + m * 32);
            rw2[m] = *(const ulonglong2*)(base + 2 * 256 * 256 + m * 32);
            rw3[m] = *(const ulonglong2*)(base + 3 * 256 * 256 + m * 32);
        }
    }

    sh[0][tid] = 0.f;
    sh[1][tid] = 0.f;
    const uint32_t locb0 = smem_u32(&bar2[0]);
    const uint32_t locb1 = smem_u32(&bar2[1]);
    if (tid == 0) {
        mbar_init(locb0, 1);
        mbar_init(locb1, 1);
        mbar_expect_tx(locb0, 1024);
        mbar_expect_tx(locb1, 1024);
    }
    __syncthreads();
    cluster_sync_();

    // store-target tables: storer lane (lane 0 of each warp) handles units
    // jj..jj+3 (16B). Even t writes sh[1]/bar1, odd t writes sh[0]/bar0.
    uint32_t dstE[8], dstO[8], brE[8], brO[8];
    {
        uint32_t aE = smem_u32(&sh[1][uglob]);   // jj%4==0 for storers
        uint32_t aO = smem_u32(&sh[0][uglob]);
        #pragma unroll
        for (int dr = 0; dr < 8; dr++) {
            dstE[dr] = mapa_sh(aE, dr);
            dstO[dr] = mapa_sh(aO, dr);
            brE[dr]  = mapa_sh(locb1, dr);
            brO[dr]  = mapa_sh(locb0, dr);
        }
    }

    float c = 0.f;
    uint32_t p0 = 0, p1 = 0;
    const bool is_writer = (oct == 0);
    const bool is_storer = ((tid & 31) == 0);   // lane 0: oct==0, jj%4==0

    for (int t = 0; t < S; t++) {
        // prefetch gate-preactivations (used by writer lanes)
        float gp0 = 0.f, gp1 = 0.f, gp2 = 0.f, gp3 = 0.f;
        if (is_writer) {
            const float* gpp = g_gpre + (size_t)t * 1024 + uglob;
            gp0 = gpp[0]; gp1 = gpp[256]; gp2 = gpp[512]; gp3 = gpp[768];
        }

        const int b = t & 1;
        if (t > 0) {
            if (b == 0) {
                mbar_wait_parity(locb0, p0); p0 ^= 1;
                if (tid == 0) mbar_expect_tx(locb0, 1024);
            } else {
                mbar_wait_parity(locb1, p1); p1 ^= 1;
                if (tid == 0) mbar_expect_tx(locb1, 1024);
            }
        }

        // matvec: 8 conflict-free LDS.128 + 64 ffma2
        const ulonglong2* hb = (const ulonglong2*)sh[b];
        ull a0 = 0, a1 = 0, a2 = 0, a3 = 0;
        #pragma unroll
        for (int m = 0; m < 8; m++) {
            ulonglong2 hv = hb[oct + m * 8];
            a0 = ffma2(hv.x, rw0[m].x, a0); a0 = ffma2(hv.y, rw0[m].y, a0);
            a1 = ffma2(hv.x, rw1[m].x, a1); a1 = ffma2(hv.y, rw1[m].y, a1);
            a2 = ffma2(hv.x, rw2[m].x, a2); a2 = ffma2(hv.y, rw2[m].y, a2);
            a3 = ffma2(hv.x, rw3[m].x, a3); a3 = ffma2(hv.y, rw3[m].y, a3);
        }
        float s0 = f2sum(a0), s1 = f2sum(a1), s2 = f2sum(a2), s3 = f2sum(a3);
        #pragma unroll
        for (int off = 1; off <= 4; off <<= 1) {
            s0 += __shfl_xor_sync(0xFFFFFFFFu, s0, off);
            s1 += __shfl_xor_sync(0xFFFFFFFFu, s1, off);
            s2 += __shfl_xor_sync(0xFFFFFFFFu, s2, off);
            s3 += __shfl_xor_sync(0xFFFFFFFFu, s3, off);
        }

        // fast epilogue (valid on oct==0 lanes; all lanes execute for shfl)
        s0 += gp0; s1 += gp1; s2 += gp2; s3 += gp3;
        c = fmaf(sigm(s1), c, sigm(s0) * tanha(s2));
        float h = sigm(s3) * tanha(c);

        // gather partner h values: units jj+1, jj+2, jj+3 live on lanes 8/16/24
        float h1 = __shfl_down_sync(0xFFFFFFFFu, h, 8);
        float h2 = __shfl_down_sync(0xFFFFFFFFu, h, 16);
        float h3 = __shfl_down_sync(0xFFFFFFFFu, h, 24);

        if (is_writer)
            g_wh[(size_t)t * HW + uglob] = h;

        if (is_storer && t < S - 1) {
            ull v0 = (ull)__float_as_uint(h)  | ((ull)__float_as_uint(h1) << 32);
            ull v1 = (ull)__float_as_uint(h2) | ((ull)__float_as_uint(h3) << 32);
            if (b == 0) {
                #pragma unroll
                for (int dr = 0; dr < 8; dr++) st_async_v2b64(dstE[dr], v0, v1, brE[dr]);
            } else {
                #pragma unroll
                for (int dr = 0; dr < 8; dr++) st_async_v2b64(dstO[dr], v0, v1, brO[dr]);
            }
        }
    }
}

// =====================================================================
// Kernel 4: tag head + log_softmax. 128 blocks x 64 tokens: tagW staged
// once per block (transposed [k][64]), warp-per-token, shfl softmax.
// =====================================================================
#define TAG_SW   (256 * 64)
#define TAG_SMEM_BYTES ((TAG_SW + 64) * 4)

__global__ void __launch_bounds__(256, 1)
tag_kernel(const float* __restrict__ tagW, const float* __restrict__ tagb,
           float* __restrict__ out)
{
    extern __shared__ float smT[];
    float* sw = smT;             // [256][64]
    float* sb = smT + TAG_SW;    // [64]

    const int tid = threadIdx.x;
    const int lane = tid & 31, warp = tid >> 5;

    for (int i = tid; i < TAG_SW; i += 256) sw[i] = 0.f;
    if (tid < 64) sb[tid] = (tid < TAGS) ? tagb[tid] : 0.f;
    __syncthreads();
    for (int i = tid; i < TAGS * 256; i += 256) {
        int tg = i >> 8, k = i & 255;
        sw[k * 64 + tg] = tagW[i];
    }
    __syncthreads();

    const bool v1 = (32 + lane) < TAGS;

    #pragma unroll 1
    for (int it = 0; it < 8; it++) {
        const int token = blockIdx.x * 64 + it * 8 + warp;
        const float4* hp4 = (const float4*)(g_wh + (size_t)token * 256);

        float a0 = 0.f, a1 = 0.f;
        #pragma unroll 8
        for (int k4 = 0; k4 < 64; k4++) {
            float4 h = hp4[k4];
            const float* p = sw + k4 * 256 + lane;
            a0 = fmaf(h.x, p[0],   a0);  a1 = fmaf(h.x, p[32],  a1);
            a0 = fmaf(h.y, p[64],  a0);  a1 = fmaf(h.y, p[96],  a1);
            a0 = fmaf(h.z, p[128], a0);  a1 = fmaf(h.z, p[160], a1);
            a0 = fmaf(h.w, p[192], a0);  a1 = fmaf(h.w, p[224], a1);
        }
        a0 += sb[lane];
        a1 += sb[32 + lane];

        float m = fmaxf(a0, v1 ? a1 : -3.4e38f);
        #pragma unroll
        for (int off = 16; off; off >>= 1)
            m = fmaxf(m, __shfl_xor_sync(0xFFFFFFFFu, m, off));
        float e = __expf(a0 - m) + (v1 ? __expf(a1 - m) : 0.f);
        #pragma unroll
        for (int off = 16; off; off >>= 1)
            e += __shfl_xor_sync(0xFFFFFFFFu, e, off);
        float ls = __logf(e);

        out[(size_t)token * TAGS + lane] = a0 - m - ls;
        if (v1) out[(size_t)token * TAGS + 32 + lane] = a1 - m - ls;
    }
}

// =====================================================================
extern "C" void kernel_launch(void* const* d_in, const int* in_sizes, int n_in,
                              void* d_out, int out_size)
{
    const int*   word_idxs = (const int*)d_in[0];
    const int*   char_idxs = (const int*)d_in[1];
    const int*   char_lens = (const int*)d_in[2];
    const float* char_emb  = (const float*)d_in[3];
    const float* char_Wih  = (const float*)d_in[4];
    const float* char_Whh  = (const float*)d_in[5];
    const float* char_bih  = (const float*)d_in[6];
    const float* char_bhh  = (const float*)d_in[7];
    const float* word_emb  = (const float*)d_in[8];
    const float* word_Wih  = (const float*)d_in[9];
    const float* word_Whh  = (const float*)d_in[10];
    const float* word_bih  = (const float*)d_in[11];
    const float* word_bhh  = (const float*)d_in[12];
    const float* tag_W     = (const float*)d_in[13];
    const float* tag_b     = (const float*)d_in[14];
    float* out = (float*)d_out;

    cudaFuncSetAttribute(char_lstm_kernel,
                         cudaFuncAttributeMaxDynamicSharedMemorySize, CHAR_SMEM_BYTES);
    cudaFuncSetAttribute(gpre_kernel,
                         cudaFuncAttributeMaxDynamicSharedMemorySize, GPRE_SMEM_BYTES);
    cudaFuncSetAttribute(tag_kernel,
                         cudaFuncAttributeMaxDynamicSharedMemorySize, TAG_SMEM_BYTES);

    char_lstm_kernel<<<256, 512, CHAR_SMEM_BYTES>>>(
        char_idxs, char_lens, char_emb, char_Wih, char_Whh, char_bih, char_bhh);

    dim3 gb(S / 16, 1024 / 64);
    gpre_kernel<<<gb, 256, GPRE_SMEM_BYTES>>>(
        word_idxs, word_emb, word_Wih, word_bih, word_bhh);

    word_lstm_kernel<<<8, 256>>>(word_Whh);

    tag_kernel<<<S / 64, 256, TAG_SMEM_BYTES>>>(tag_W, tag_b, out);
}

// round 5
// speedup vs baseline: 1.1456x; 1.1456x over previous
#include <cuda_runtime.h>
#include <cstdint>
#include <cstddef>

#define S     8192
#define LC    16
#define CH    64
#define HW    256
#define TAGS  50

typedef unsigned long long ull;

// ---------------- device scratch ----------------
__device__ __align__(256) float g_char_feat[S * CH];        // 2 MB
__device__ __align__(256) float g_gpre[(size_t)S * 4 * HW]; // 32 MB
__device__ __align__(256) float g_wh[(size_t)S * HW];       // 8 MB

// ---------------- helpers ----------------
__device__ __forceinline__ ull ffma2(ull a, ull b, ull c) {
    ull d;
    asm("fma.rn.f32x2 %0, %1, %2, %3;" : "=l"(d) : "l"(a), "l"(b), "l"(c));
    return d;
}
__device__ __forceinline__ float f2sum(ull a) {
    float lo = __uint_as_float((unsigned)(a & 0xffffffffull));
    float hi = __uint_as_float((unsigned)(a >> 32));
    return lo + hi;
}
__device__ __forceinline__ float tanha(float x) {
    float y; asm("tanh.approx.f32 %0, %1;" : "=f"(y) : "f"(x)); return y;
}
__device__ __forceinline__ float sigm(float x) {       // 1 MUFU
    return fmaf(0.5f, tanha(0.5f * x), 0.5f);
}
__device__ __forceinline__ uint32_t smem_u32(const void* p) {
    return (uint32_t)__cvta_generic_to_shared(p);
}
__device__ __forceinline__ uint32_t cluster_rank() {
    uint32_t r; asm("mov.u32 %0, %%cluster_ctarank;" : "=r"(r)); return r;
}
__device__ __forceinline__ uint32_t mapa_sh(uint32_t addr, uint32_t rank) {
    uint32_t r;
    asm("mapa.shared::cluster.u32 %0, %1, %2;" : "=r"(r) : "r"(addr), "r"(rank));
    return r;
}
__device__ __forceinline__ void mbar_init(uint32_t addr, uint32_t cnt) {
    asm volatile("mbarrier.init.shared.b64 [%0], %1;" :: "r"(addr), "r"(cnt) : "memory");
}
__device__ __forceinline__ void mbar_expect_tx(uint32_t addr, uint32_t bytes) {
    asm volatile("mbarrier.arrive.expect_tx.shared.b64 _, [%0], %1;"
                 :: "r"(addr), "r"(bytes) : "memory");
}
__device__ __forceinline__ void st_async_b32(uint32_t dst, float v, uint32_t mbar) {
    asm volatile("st.async.shared::cluster.mbarrier::complete_tx::bytes.b32 [%0], %1, [%2];"
                 :: "r"(dst), "r"(__float_as_uint(v)), "r"(mbar) : "memory");
}
__device__ __forceinline__ void mbar_wait_parity(uint32_t mbar, uint32_t parity) {
    asm volatile(
        "{\n\t.reg .pred P;\n"
        "W%=:\n\t"
        "mbarrier.try_wait.parity.acquire.cluster.shared::cta.b64 P, [%0], %1, 0x989680;\n\t"
        "@!P bra W%=;\n\t"
        "}" :: "r"(mbar), "r"(parity) : "memory");
}
__device__ __forceinline__ void cluster_sync_() {
    asm volatile("barrier.cluster.arrive.aligned;\n\tbarrier.cluster.wait.aligned;" ::: "memory");
}

// =====================================================================
// Kernel 1: char LSTM
// =====================================================================
#define CA_SW   (512 * 68)
#define CA_EMB  (128 * 64)
#define CA_HB   (32 * 64)
#define CA_SB   256
#define CHAR_SMEM_BYTES ((CA_SW + CA_EMB + CA_HB + CA_SB) * 4 + 512 * 4)

__global__ void __launch_bounds__(512, 1)
char_lstm_kernel(const int* __restrict__ ci_g, const int* __restrict__ clen,
                 const float* __restrict__ cemb_g,
                 const float* __restrict__ Wih, const float* __restrict__ Whh,
                 const float* __restrict__ bih, const float* __restrict__ bhh)
{
    extern __shared__ float smA[];
    float* sW    = smA;
    float* cemb  = sW + CA_SW;
    float* hbuf  = cemb + CA_EMB;
    float* sb    = hbuf + CA_HB;
    int*   scidx = (int*)(sb + CA_SB);

    const int tid = threadIdx.x;
    const int wbase = blockIdx.x * 32;

    for (int idx = tid; idx < 512 * 16; idx += 512) {
        int row = idx >> 4, k4 = idx & 15;
        const float* src = (row < 256) ? Wih + (size_t)row * 64 + k4 * 4
                                       : Whh + (size_t)(row - 256) * 64 + k4 * 4;
        *(float4*)&sW[row * 68 + k4 * 4] = *(const float4*)src;
    }
    for (int idx = tid; idx < 128 * 16; idx += 512) {
        int row = idx >> 4, k4 = idx & 15;
        *(float4*)&cemb[row * 64 + k4 * 4] = *(const float4*)(cemb_g + (size_t)row * 64 + k4 * 4);
    }
    if (tid < 256) sb[tid] = bih[tid] + bhh[tid];
    scidx[tid] = ci_g[(size_t)wbase * 16 + tid];
    for (int idx = tid; idx < CA_HB; idx += 512) hbuf[idx] = 0.f;

    const int rt = tid & 63, wt = tid >> 6, w0 = wt * 4;
    int len[4]; float cc[4];
    #pragma unroll
    for (int i = 0; i < 4; i++) { len[i] = clen[wbase + w0 + i]; cc[i] = 0.f; }
    __syncthreads();

    for (int t = 0; t < LC; t++) {
        int ci[4];
        #pragma unroll
        for (int i = 0; i < 4; i++) ci[i] = scidx[(w0 + i) * 16 + t];

        ull acc[4][4];
        #pragma unroll
        for (int i = 0; i < 4; i++)
            #pragma unroll
            for (int q = 0; q < 4; q++) acc[i][q] = 0ull;

        #pragma unroll
        for (int k4 = 0; k4 < 16; k4++) {
            ulonglong2 wv[4];
            #pragma unroll
            for (int q = 0; q < 4; q++)
                wv[q] = *(const ulonglong2*)&sW[(q * 64 + rt) * 68 + k4 * 4];
            #pragma unroll
            for (int i = 0; i < 4; i++) {
                ulonglong2 xv = *(const ulonglong2*)&cemb[ci[i] * 64 + k4 * 4];
                #pragma unroll
                for (int q = 0; q < 4; q++) {
                    acc[i][q] = ffma2(xv.x, wv[q].x, acc[i][q]);
                    acc[i][q] = ffma2(xv.y, wv[q].y, acc[i][q]);
                }
            }
        }
        #pragma unroll
        for (int k4 = 0; k4 < 16; k4++) {
            ulonglong2 wv[4];
            #pragma unroll
            for (int q = 0; q < 4; q++)
                wv[q] = *(const ulonglong2*)&sW[(256 + q * 64 + rt) * 68 + k4 * 4];
            #pragma unroll
            for (int i = 0; i < 4; i++) {
                ulonglong2 hv = *(const ulonglong2*)&hbuf[(w0 + i) * 64 + k4 * 4];
                #pragma unroll
                for (int q = 0; q < 4; q++) {
                    acc[i][q] = ffma2(hv.x, wv[q].x, acc[i][q]);
                    acc[i][q] = ffma2(hv.y, wv[q].y, acc[i][q]);
                }
            }
        }
        __syncthreads();

        float bI = sb[rt], bF = sb[64 + rt], bG = sb[128 + rt], bO = sb[192 + rt];
        #pragma unroll
        for (int i = 0; i < 4; i++) {
            float gi = f2sum(acc[i][0]) + bI;
            float gf = f2sum(acc[i][1]) + bF;
            float gG = f2sum(acc[i][2]) + bG;
            float go = f2sum(acc[i][3]) + bO;
            cc[i] = fmaf(sigm(gf), cc[i], sigm(gi) * tanha(gG));
            float h = sigm(go) * tanha(cc[i]);
            hbuf[(w0 + i) * 64 + rt] = h;
            if (t == len[i] - 1)
                g_char_feat[(size_t)(wbase + w0 + i) * 64 + rt] = h;
        }
        __syncthreads();
    }
}

// =====================================================================
// Kernel 2: gpre
// =====================================================================
#define BP 196
#define GPRE_SMEM_BYTES ((16 + 64) * BP * 4)

__global__ void __launch_bounds__(256, 1)
gpre_kernel(const int* __restrict__ widx, const float* __restrict__ wemb,
            const float* __restrict__ Wih,
            const float* __restrict__ bih, const float* __restrict__ bhh)
{
    extern __shared__ float smB[];
    float* sx = smB;
    float* sw = smB + 16 * BP;

    const int tid = threadIdx.x;
    const int t0 = blockIdx.x * 16;
    const int G0 = blockIdx.y * 64;

    for (int i = tid; i < 16 * 48; i += 256) {
        int tt = i / 48, k4 = i % 48;
        float4 v = (k4 < 32)
            ? *(const float4*)(wemb + (size_t)widx[t0 + tt] * 128 + k4 * 4)
            : *(const float4*)(g_char_feat + (size_t)(t0 + tt) * 64 + (k4 - 32) * 4);
        *(float4*)&sx[tt * BP + k4 * 4] = v;
    }
    for (int i = tid; i < 64 * 48; i += 256) {
        int r = i / 48, k4 = i % 48;
        *(float4*)&sw[r * BP + k4 * 4] = *(const float4*)(Wih + (size_t)(G0 + r) * 192 + k4 * 4);
    }
    __syncthreads();

    const int g = tid & 63, tq = tid >> 6;
    ull ax[4], ay[4];
    #pragma unroll
    for (int i = 0; i < 4; i++) { ax[i] = 0ull; ay[i] = 0ull; }

    #pragma unroll 4
    for (int k4 = 0; k4 < 48; k4++) {
        ulonglong2 wv = *(const ulonglong2*)&sw[g * BP + k4 * 4];
        #pragma unroll
        for (int it = 0; it < 4; it++) {
            ulonglong2 xv = *(const ulonglong2*)&sx[(tq * 4 + it) * BP + k4 * 4];
            ax[it] = ffma2(xv.x, wv.x, ax[it]);
            ay[it] = ffma2(xv.y, wv.y, ay[it]);
        }
    }
    float b = bih[G0 + g] + bhh[G0 + g];
    #pragma unroll
    for (int it = 0; it < 4; it++)
        g_gpre[(size_t)(t0 + tq * 4 + it) * 1024 + G0 + g] = f2sum(ax[it]) + f2sum(ay[it]) + b;
}

// =====================================================================
// Kernel 3: word LSTM. 8-CTA cluster, st.async tx barriers.
// Broadcast: each writer lane (oct==0, 32 per CTA) fires its own
// st.async.b32 to all 8 dest CTAs immediately after computing h —
// zero gather shuffles on the critical path.
// =====================================================================
__global__ void __launch_bounds__(256, 1) __cluster_dims__(8, 1, 1)
word_lstm_kernel(const float* __restrict__ Whh)
{
    __shared__ float sh[2][256];
    __shared__ __align__(8) unsigned long long bar2[2];

    const int tid = threadIdx.x;
    const int jj  = tid >> 3;     // 0..31 h-unit
    const int oct = tid & 7;      // k octant
    const uint32_t rank = cluster_rank();
    const int uglob = (int)rank * 32 + jj;

    // weights: rw[q][m] covers gate row (q*256 + uglob), k = oct*4 + m*32
    ulonglong2 rw0[8], rw1[8], rw2[8], rw3[8];
    {
        const float* base = Whh + (size_t)uglob * 256 + oct * 4;
        #pragma unroll
        for (int m = 0; m < 8; m++) {
            rw0[m] = *(const ulonglong2*)(base + 0 * 256 * 256 + m * 32);
            rw1[m] = *(const ulonglong2*)(base + 1 * 256 * 256 + m * 32);
            rw2[m] = *(const ulonglong2*)(base + 2 * 256 * 256 + m * 32);
            rw3[m] = *(const ulonglong2*)(base + 3 * 256 * 256 + m * 32);
        }
    }

    sh[0][tid] = 0.f;
    sh[1][tid] = 0.f;
    const uint32_t locb0 = smem_u32(&bar2[0]);
    const uint32_t locb1 = smem_u32(&bar2[1]);
    if (tid == 0) {
        mbar_init(locb0, 1);
        mbar_init(locb1, 1);
        mbar_expect_tx(locb0, 1024);
        mbar_expect_tx(locb1, 1024);
    }
    __syncthreads();
    cluster_sync_();

    // per-writer store tables: unit uglob's slot in every dest CTA
    uint32_t dstE[8], dstO[8], brE[8], brO[8];
    {
        uint32_t aE = smem_u32(&sh[1][uglob]);
        uint32_t aO = smem_u32(&sh[0][uglob]);
        #pragma unroll
        for (int dr = 0; dr < 8; dr++) {
            dstE[dr] = mapa_sh(aE, dr);
            dstO[dr] = mapa_sh(aO, dr);
            brE[dr]  = mapa_sh(locb1, dr);
            brO[dr]  = mapa_sh(locb0, dr);
        }
    }

    float c = 0.f;
    uint32_t p0 = 0, p1 = 0;
    const bool is_writer = (oct == 0);

    for (int t = 0; t < S; t++) {
        // prefetch gate-preactivations (used by writer lanes; overlaps wait)
        float gp0 = 0.f, gp1 = 0.f, gp2 = 0.f, gp3 = 0.f;
        if (is_writer) {
            const float* gpp = g_gpre + (size_t)t * 1024 + uglob;
            gp0 = gpp[0]; gp1 = gpp[256]; gp2 = gpp[512]; gp3 = gpp[768];
        }

        const int b = t & 1;
        if (t > 0) {
            if (b == 0) {
                mbar_wait_parity(locb0, p0); p0 ^= 1;
                if (tid == 0) mbar_expect_tx(locb0, 1024);
            } else {
                mbar_wait_parity(locb1, p1); p1 ^= 1;
                if (tid == 0) mbar_expect_tx(locb1, 1024);
            }
        }

        // matvec: 8 conflict-free LDS.128 + 64 ffma2
        const ulonglong2* hb = (const ulonglong2*)sh[b];
        ull a0 = 0, a1 = 0, a2 = 0, a3 = 0;
        #pragma unroll
        for (int m = 0; m < 8; m++) {
            ulonglong2 hv = hb[oct + m * 8];
            a0 = ffma2(hv.x, rw0[m].x, a0); a0 = ffma2(hv.y, rw0[m].y, a0);
            a1 = ffma2(hv.x, rw1[m].x, a1); a1 = ffma2(hv.y, rw1[m].y, a1);
            a2 = ffma2(hv.x, rw2[m].x, a2); a2 = ffma2(hv.y, rw2[m].y, a2);
            a3 = ffma2(hv.x, rw3[m].x, a3); a3 = ffma2(hv.y, rw3[m].y, a3);
        }
        float s0 = f2sum(a0), s1 = f2sum(a1), s2 = f2sum(a2), s3 = f2sum(a3);
        #pragma unroll
        for (int off = 1; off <= 4; off <<= 1) {
            s0 += __shfl_xor_sync(0xFFFFFFFFu, s0, off);
            s1 += __shfl_xor_sync(0xFFFFFFFFu, s1, off);
            s2 += __shfl_xor_sync(0xFFFFFFFFu, s2, off);
            s3 += __shfl_xor_sync(0xFFFFFFFFu, s3, off);
        }

        // fast epilogue (valid on oct==0 lanes)
        s0 += gp0; s1 += gp1; s2 += gp2; s3 += gp3;
        c = fmaf(sigm(s1), c, sigm(s0) * tanha(s2));
        float h = sigm(s3) * tanha(c);

        if (is_writer) {
            if (t < S - 1) {
                // fabric first: broadcast h to all CTAs' next-step buffer
                if (b == 0) {
                    #pragma unroll
                    for (int dr = 0; dr < 8; dr++) st_async_b32(dstE[dr], h, brE[dr]);
                } else {
                    #pragma unroll
                    for (int dr = 0; dr < 8; dr++) st_async_b32(dstO[dr], h, brO[dr]);
                }
            }
            g_wh[(size_t)t * HW + uglob] = h;
        }
    }
}

// =====================================================================
// Kernel 4: tag head + log_softmax. 128 blocks x 64 tokens, tagW staged
// once per block (transposed [k][64]), warp-per-token, shfl softmax.
// =====================================================================
#define TAG_SW   (256 * 64)
#define TAG_SMEM_BYTES ((TAG_SW + 64) * 4)

__global__ void __launch_bounds__(256, 1)
tag_kernel(const float* __restrict__ tagW, const float* __restrict__ tagb,
           float* __restrict__ out)
{
    extern __shared__ float smT[];
    float* sw = smT;             // [256][64]
    float* sb = smT + TAG_SW;    // [64]

    const int tid = threadIdx.x;
    const int lane = tid & 31, warp = tid >> 5;

    for (int i = tid; i < TAG_SW; i += 256) sw[i] = 0.f;
    if (tid < 64) sb[tid] = (tid < TAGS) ? tagb[tid] : 0.f;
    __syncthreads();
    for (int i = tid; i < TAGS * 256; i += 256) {
        int tg = i >> 8, k = i & 255;
        sw[k * 64 + tg] = tagW[i];
    }
    __syncthreads();

    const bool v1 = (32 + lane) < TAGS;

    #pragma unroll 1
    for (int it = 0; it < 8; it++) {
        const int token = blockIdx.x * 64 + it * 8 + warp;
        const float4* hp4 = (const float4*)(g_wh + (size_t)token * 256);

        float a0 = 0.f, a1 = 0.f;
        #pragma unroll 8
        for (int k4 = 0; k4 < 64; k4++) {
            float4 h = hp4[k4];
            const float* p = sw + k4 * 256 + lane;
            a0 = fmaf(h.x, p[0],   a0);  a1 = fmaf(h.x, p[32],  a1);
            a0 = fmaf(h.y, p[64],  a0);  a1 = fmaf(h.y, p[96],  a1);
            a0 = fmaf(h.z, p[128], a0);  a1 = fmaf(h.z, p[160], a1);
            a0 = fmaf(h.w, p[192], a0);  a1 = fmaf(h.w, p[224], a1);
        }
        a0 += sb[lane];
        a1 += sb[32 + lane];

        float m = fmaxf(a0, v1 ? a1 : -3.4e38f);
        #pragma unroll
        for (int off = 16; off; off >>= 1)
            m = fmaxf(m, __shfl_xor_sync(0xFFFFFFFFu, m, off));
        float e = __expf(a0 - m) + (v1 ? __expf(a1 - m) : 0.f);
        #pragma unroll
        for (int off = 16; off; off >>= 1)
            e += __shfl_xor_sync(0xFFFFFFFFu, e, off);
        float ls = __logf(e);

        out[(size_t)token * TAGS + lane] = a0 - m - ls;
        if (v1) out[(size_t)token * TAGS + 32 + lane] = a1 - m - ls;
    }
}

// =====================================================================
extern "C" void kernel_launch(void* const* d_in, const int* in_sizes, int n_in,
                              void* d_out, int out_size)
{
    const int*   word_idxs = (const int*)d_in[0];
    const int*   char_idxs = (const int*)d_in[1];
    const int*   char_lens = (const int*)d_in[2];
    const float* char_emb  = (const float*)d_in[3];
    const float* char_Wih  = (const float*)d_in[4];
    const float* char_Whh  = (const float*)d_in[5];
    const float* char_bih  = (const float*)d_in[6];
    const float* char_bhh  = (const float*)d_in[7];
    const float* word_emb  = (const float*)d_in[8];
    const float* word_Wih  = (const float*)d_in[9];
    const float* word_Whh  = (const float*)d_in[10];
    const float* word_bih  = (const float*)d_in[11];
    const float* word_bhh  = (const float*)d_in[12];
    const float* tag_W     = (const float*)d_in[13];
    const float* tag_b     = (const float*)d_in[14];
    float* out = (float*)d_out;

    cudaFuncSetAttribute(char_lstm_kernel,
                         cudaFuncAttributeMaxDynamicSharedMemorySize, CHAR_SMEM_BYTES);
    cudaFuncSetAttribute(gpre_kernel,
                         cudaFuncAttributeMaxDynamicSharedMemorySize, GPRE_SMEM_BYTES);
    cudaFuncSetAttribute(tag_kernel,
                         cudaFuncAttributeMaxDynamicSharedMemorySize, TAG_SMEM_BYTES);

    char_lstm_kernel<<<256, 512, CHAR_SMEM_BYTES>>>(
        char_idxs, char_lens, char_emb, char_Wih, char_Whh, char_bih, char_bhh);

    dim3 gb(S / 16, 1024 / 64);
    gpre_kernel<<<gb, 256, GPRE_SMEM_BYTES>>>(
        word_idxs, word_emb, word_Wih, word_bih, word_bhh);

    word_lstm_kernel<<<8, 256>>>(word_Whh);

    tag_kernel<<<S / 64, 256, TAG_SMEM_BYTES>>>(tag_W, tag_b, out);
}